// round 14
// baseline (speedup 1.0000x reference)
#include <cuda_runtime.h>
#include <cuda_fp16.h>
#include <math.h>

#define NMAXN 100000
#define NMAXE 1600000
#define INCH 61
#define OC 64
#define BN_EPS 1e-5f
#define SCAN_BLK 1024

// ------------- static device scratch (no allocation allowed) -------------
__device__ uint4  d_Ah[NMAXN * 8];    // 64 ch fp16 per node (128 B)
__device__ float4 d_Bp4[NMAXN * 16];  // pos @ W1[61:64], fp32
__device__ int    d_deg[NMAXN];
__device__ int    d_odeg[NMAXN];
__device__ float  d_V[NMAXN * 3];
__device__ int    d_scanned[NMAXN];
__device__ int    d_bsum[128];
__device__ int    d_rowptr[NMAXN + 1];
__device__ int    d_cursor[NMAXN];
__device__ int    d_csrc[NMAXE];
__device__ float  d_graw[NMAXE];
__device__ float  d_s1[OC];
__device__ float  d_s2[OC];
__device__ float  d_s3[OC];
__device__ float  d_s4[OC];
__device__ float  d_s5[OC];
__device__ float4 d_scale1[16];
__device__ float4 d_shift1[16];       // FOLDED: beta + (b1 - mu)*sc
__device__ float  d_gstats[2];
__device__ float  d_gparams[2];

// ------------- host-side streams/events for branched graph capture -------------
struct ForkResources {
    cudaStream_t s;
    cudaEvent_t  fork, ecnt, join;
    ForkResources() {
        cudaStreamCreateWithFlags(&s, cudaStreamNonBlocking);
        cudaEventCreateWithFlags(&fork, cudaEventDisableTiming);
        cudaEventCreateWithFlags(&ecnt, cudaEventDisableTiming);
        cudaEventCreateWithFlags(&join, cudaEventDisableTiming);
    }
};
static ForkResources g_fr;

__device__ __forceinline__ float silu_f(float t) {
    float u = 0.5f * t;
    float v;
    asm("tanh.approx.f32 %0, %1;" : "=f"(v) : "f"(u));
    return fmaf(u, v, u);
}

// dot over 8 channels: silu(fmaf(a, sc, o)) . wg
__device__ __forceinline__ float dot8(const uint4& raw,
                                      const float4& oA, const float4& oB,
                                      const float4& scA, const float4& scB,
                                      const float4& wgA, const float4& wgB) {
    const __half2* hp = (const __half2*)&raw;
    float2 a01 = __half22float2(hp[0]);
    float2 a23 = __half22float2(hp[1]);
    float2 a45 = __half22float2(hp[2]);
    float2 a67 = __half22float2(hp[3]);
    return silu_f(fmaf(a01.x, scA.x, oA.x)) * wgA.x
         + silu_f(fmaf(a01.y, scA.y, oA.y)) * wgA.y
         + silu_f(fmaf(a23.x, scA.z, oA.z)) * wgA.z
         + silu_f(fmaf(a23.y, scA.w, oA.w)) * wgA.w
         + silu_f(fmaf(a45.x, scB.x, oB.x)) * wgB.x
         + silu_f(fmaf(a45.y, scB.y, oB.y)) * wgB.y
         + silu_f(fmaf(a67.x, scB.z, oB.z)) * wgB.z
         + silu_f(fmaf(a67.y, scB.w, oB.w)) * wgB.w;
}

// accA/accB += w * silu(fmaf(a, sc, o)) over 8 channels
__device__ __forceinline__ void acc8(const uint4& raw,
                                     const float4& oA, const float4& oB,
                                     const float4& scA, const float4& scB,
                                     float w, float4& accA, float4& accB) {
    const __half2* hp = (const __half2*)&raw;
    float2 a01 = __half22float2(hp[0]);
    float2 a23 = __half22float2(hp[1]);
    float2 a45 = __half22float2(hp[2]);
    float2 a67 = __half22float2(hp[3]);
    accA.x = fmaf(w, silu_f(fmaf(a01.x, scA.x, oA.x)), accA.x);
    accA.y = fmaf(w, silu_f(fmaf(a01.y, scA.y, oA.y)), accA.y);
    accA.z = fmaf(w, silu_f(fmaf(a23.x, scA.z, oA.z)), accA.z);
    accA.w = fmaf(w, silu_f(fmaf(a23.y, scA.w, oA.w)), accA.w);
    accB.x = fmaf(w, silu_f(fmaf(a45.x, scB.x, oB.x)), accB.x);
    accB.y = fmaf(w, silu_f(fmaf(a45.y, scB.y, oB.y)), accB.y);
    accB.z = fmaf(w, silu_f(fmaf(a67.x, scB.z, oB.z)), accB.z);
    accB.w = fmaf(w, silu_f(fmaf(a67.y, scB.w, oB.w)), accB.w);
}

// ------------- K0 -------------
__global__ void k_init(int n) {
    int i = blockIdx.x * blockDim.x + threadIdx.x;
    int st = gridDim.x * blockDim.x;
    for (int t = i; t < n; t += st) { d_deg[t] = 0; d_odeg[t] = 0; }
    for (int t = i; t < 3 * n; t += st) d_V[t] = 0.f;
    if (i < OC) { d_s1[i] = 0.f; d_s2[i] = 0.f; d_s3[i] = 0.f; d_s4[i] = 0.f; d_s5[i] = 0.f; }
    if (i < 2)  { d_gstats[i] = 0.f; }
}

// ------------- K1: per-node transform -------------
__global__ void k_node(const float* __restrict__ x, const float* __restrict__ pos,
                       const float* __restrict__ W1, int n) {
    __shared__ float2 sW[64 * 32];
    const float2* W2 = (const float2*)W1;
    for (int i = threadIdx.x; i < 64 * 32; i += blockDim.x) sW[i] = W2[i];
    __syncthreads();
    int lane = threadIdx.x & 31;
    int wid  = (blockIdx.x * blockDim.x + threadIdx.x) >> 5;
    int nw   = (gridDim.x * blockDim.x) >> 5;
    __half2* Ah2 = (__half2*)d_Ah;
    float2*  Bp2 = (float2*)d_Bp4;
    for (int nd = wid; nd < n; nd += nw) {
        float a0 = 0.f, a1 = 0.f, b0 = 0.f, b1v = 0.f;
        const float* xr = x + (long long)nd * INCH;
        #pragma unroll
        for (int k = 0; k < INCH; k++) {
            float xv = __ldg(xr + k);
            float2 w = sW[k * 32 + lane];
            a0 = fmaf(xv, w.x, a0);
            a1 = fmaf(xv, w.y, a1);
        }
        const float* pr = pos + (long long)nd * 3;
        #pragma unroll
        for (int k = 0; k < 3; k++) {
            float pv = __ldg(pr + k);
            float2 w = sW[(INCH + k) * 32 + lane];
            b0  = fmaf(pv, w.x, b0);
            b1v = fmaf(pv, w.y, b1v);
        }
        Ah2[nd * 32 + lane] = __floats2half2_rn(a0 + b0, a1 + b1v);
        Bp2[nd * 32 + lane] = make_float2(b0, b1v);
    }
}

// ------------- K2: degree histograms + V accumulation -------------
__global__ void k_count(const int* __restrict__ ei, const float* __restrict__ pos,
                        int e, int n) {
    int i = blockIdx.x * blockDim.x + threadIdx.x;
    int st = gridDim.x * blockDim.x;
    for (; i < e; i += st) {
        unsigned s = (unsigned)ei[i];
        unsigned d = (unsigned)ei[e + i];
        if (s >= (unsigned)n || d >= (unsigned)n) continue;
        atomicAdd(&d_deg[d], 1);
        atomicAdd(&d_odeg[s], 1);
        const float* pd = pos + (size_t)d * 3;
        atomicAdd(&d_V[s * 3 + 0], pd[0]);
        atomicAdd(&d_V[s * 3 + 1], pd[1]);
        atomicAdd(&d_V[s * 3 + 2], pd[2]);
    }
}

// ------------- K3a -------------
__global__ void k_scanA(int n) {
    __shared__ int sh[32];
    int t = threadIdx.x, lane = t & 31, w = t >> 5;
    int idx = blockIdx.x * SCAN_BLK + t;
    int v = (idx < n) ? d_deg[idx] : 0;
    int xv = v;
    #pragma unroll
    for (int off = 1; off < 32; off <<= 1) {
        int y = __shfl_up_sync(0xffffffffu, xv, off);
        if (lane >= off) xv += y;
    }
    if (lane == 31) sh[w] = xv;
    __syncthreads();
    if (w == 0) {
        int y2 = sh[lane];
        #pragma unroll
        for (int off = 1; off < 32; off <<= 1) {
            int z = __shfl_up_sync(0xffffffffu, y2, off);
            if (lane >= off) y2 += z;
        }
        sh[lane] = y2;
    }
    __syncthreads();
    int incl = xv + ((w > 0) ? sh[w - 1] : 0);
    if (idx < n) d_scanned[idx] = incl;
    if (t == SCAN_BLK - 1) d_bsum[blockIdx.x] = incl;
}

// ------------- K3b -------------
__global__ void k_scanB(int nb, int n) {
    __shared__ int sw[4];
    int t = threadIdx.x, lane = t & 31, w = t >> 5;
    int v = (t < nb) ? d_bsum[t] : 0;
    int xv = v;
    #pragma unroll
    for (int off = 1; off < 32; off <<= 1) {
        int y = __shfl_up_sync(0xffffffffu, xv, off);
        if (lane >= off) xv += y;
    }
    if (lane == 31) sw[w] = xv;
    __syncthreads();
    if (t == 0) {
        int run = 0;
        #pragma unroll
        for (int i = 0; i < 4; i++) { int tmp = sw[i]; sw[i] = run; run += tmp; }
    }
    __syncthreads();
    int incl = xv + sw[w];
    if (t < nb) d_bsum[t] = incl - v;
    if (t == nb - 1) d_rowptr[n] = incl;
}

// ------------- K3c -------------
__global__ void k_scanC(int n) {
    int idx = blockIdx.x * SCAN_BLK + threadIdx.x;
    if (idx < n) {
        int ex = d_scanned[idx] - d_deg[idx] + d_bsum[blockIdx.x];
        d_rowptr[idx] = ex;
        d_cursor[idx] = ex;
    }
}

// ------------- K4: scatter src ids into CSR slots -------------
__global__ void k_scatter(const int* __restrict__ ei, int e, int n) {
    int i = blockIdx.x * blockDim.x + threadIdx.x;
    int st = gridDim.x * blockDim.x;
    for (; i < e; i += st) {
        unsigned s = (unsigned)ei[i];
        unsigned d = (unsigned)ei[e + i];
        if (s >= (unsigned)n || d >= (unsigned)n) continue;
        int p = atomicAdd(&d_cursor[d], 1);
        d_csrc[p] = (int)s;
    }
}

// ------------- K5: node-level BN1 stats (wide grid, 2-node ILP) -------------
__global__ void k_zstats(const float* __restrict__ b1, const float* __restrict__ W1, int n) {
    int lane = threadIdx.x & 31;
    int wid  = (blockIdx.x * blockDim.x + threadIdx.x) >> 5;
    int nw   = (gridDim.x * blockDim.x) >> 5;
    const __half2* Ah2 = (const __half2*)d_Ah;
    const float2*  Bp2 = (const float2*)d_Bp4;
    float2 bias = ((const float2*)b1)[lane];
    float2 w61 = ((const float2*)(W1 + 61 * OC))[lane];
    float2 w62 = ((const float2*)(W1 + 62 * OC))[lane];
    float2 w63 = ((const float2*)(W1 + 63 * OC))[lane];
    float s1x = 0.f, s1y = 0.f, s2x = 0.f, s2y = 0.f, s3x = 0.f, s3y = 0.f;
    float s4x = 0.f, s4y = 0.f, s5x = 0.f, s5y = 0.f;
    int nd = wid;
    // 2 nodes per iteration: all loads issued before arithmetic (MLP 2x)
    for (; nd + nw < n; nd += 2 * nw) {
        int nd2 = nd + nw;
        float odA = (float)d_odeg[nd],  odB = (float)d_odeg[nd2];
        float idA = (float)d_deg[nd],   idB = (float)d_deg[nd2];
        float2 aA  = __half22float2(Ah2[nd * 32 + lane]);
        float2 aB  = __half22float2(Ah2[nd2 * 32 + lane]);
        float2 bpA = Bp2[nd * 32 + lane];
        float2 bpB = Bp2[nd2 * 32 + lane];
        float vA0 = d_V[nd * 3 + 0],  vA1 = d_V[nd * 3 + 1],  vA2 = d_V[nd * 3 + 2];
        float vB0 = d_V[nd2 * 3 + 0], vB1 = d_V[nd2 * 3 + 1], vB2 = d_V[nd2 * 3 + 2];
        s1x = fmaf(odA, aA.x, s1x);         s1y = fmaf(odA, aA.y, s1y);
        s2x = fmaf(idA, bpA.x, s2x);        s2y = fmaf(idA, bpA.y, s2y);
        s3x = fmaf(odA * aA.x, aA.x, s3x);  s3y = fmaf(odA * aA.y, aA.y, s3y);
        float oAx = bias.x - bpA.x, oAy = bias.y - bpA.y;
        s4x = fmaf(idA * oAx, oAx, s4x);    s4y = fmaf(idA * oAy, oAy, s4y);
        float bvAx = vA0 * w61.x + vA1 * w62.x + vA2 * w63.x;
        float bvAy = vA0 * w61.y + vA1 * w62.y + vA2 * w63.y;
        s5x = fmaf(aA.x, bvAx, s5x);        s5y = fmaf(aA.y, bvAy, s5y);
        s1x = fmaf(odB, aB.x, s1x);         s1y = fmaf(odB, aB.y, s1y);
        s2x = fmaf(idB, bpB.x, s2x);        s2y = fmaf(idB, bpB.y, s2y);
        s3x = fmaf(odB * aB.x, aB.x, s3x);  s3y = fmaf(odB * aB.y, aB.y, s3y);
        float oBx = bias.x - bpB.x, oBy = bias.y - bpB.y;
        s4x = fmaf(idB * oBx, oBx, s4x);    s4y = fmaf(idB * oBy, oBy, s4y);
        float bvBx = vB0 * w61.x + vB1 * w62.x + vB2 * w63.x;
        float bvBy = vB0 * w61.y + vB1 * w62.y + vB2 * w63.y;
        s5x = fmaf(aB.x, bvBx, s5x);        s5y = fmaf(aB.y, bvBy, s5y);
    }
    if (nd < n) {
        float od = (float)d_odeg[nd];
        float id = (float)d_deg[nd];
        float2 a  = __half22float2(Ah2[nd * 32 + lane]);
        float2 bp = Bp2[nd * 32 + lane];
        float v0 = d_V[nd * 3 + 0], v1 = d_V[nd * 3 + 1], v2 = d_V[nd * 3 + 2];
        s1x = fmaf(od, a.x, s1x);          s1y = fmaf(od, a.y, s1y);
        s2x = fmaf(id, bp.x, s2x);         s2y = fmaf(id, bp.y, s2y);
        s3x = fmaf(od * a.x, a.x, s3x);    s3y = fmaf(od * a.y, a.y, s3y);
        float ox = bias.x - bp.x, oy = bias.y - bp.y;
        s4x = fmaf(id * ox, ox, s4x);      s4y = fmaf(id * oy, oy, s4y);
        float bvx = v0 * w61.x + v1 * w62.x + v2 * w63.x;
        float bvy = v0 * w61.y + v1 * w62.y + v2 * w63.y;
        s5x = fmaf(a.x, bvx, s5x);         s5y = fmaf(a.y, bvy, s5y);
    }
    atomicAdd(&d_s1[2 * lane], s1x);     atomicAdd(&d_s1[2 * lane + 1], s1y);
    atomicAdd(&d_s2[2 * lane], s2x);     atomicAdd(&d_s2[2 * lane + 1], s2y);
    atomicAdd(&d_s3[2 * lane], s3x);     atomicAdd(&d_s3[2 * lane + 1], s3y);
    atomicAdd(&d_s4[2 * lane], s4x);     atomicAdd(&d_s4[2 * lane + 1], s4y);
    atomicAdd(&d_s5[2 * lane], s5x);     atomicAdd(&d_s5[2 * lane + 1], s5y);
}

// ------------- K6: finalize BN1 params (b1 folded into shift) -------------
__global__ void k_bn1(const float* __restrict__ g1, const float* __restrict__ be1,
                      const float* __restrict__ b1, float Ef) {
    int c = threadIdx.x;
    float bc = b1[c];
    float sumz  = d_s1[c] + Ef * bc - d_s2[c];
    float sumz2 = d_s3[c] + d_s4[c] + 2.0f * (bc * d_s1[c] - d_s5[c]);
    float mu  = sumz / Ef;
    float var = sumz2 / Ef - mu * mu;
    float sc  = g1[c] * rsqrtf(var + BN_EPS);
    ((float*)d_scale1)[c] = sc;
    ((float*)d_shift1)[c] = be1[c] + (bc - mu) * sc;
}

// ------------- K7: gate (quarter-warp per edge, 8 edges/iter) -------------
__global__ void k_gate(const float* __restrict__ Wg, const float* __restrict__ bg, int n) {
    int lane = threadIdx.x & 31;
    int q  = lane >> 3;
    int ql = lane & 7;
    int wid  = (blockIdx.x * blockDim.x + threadIdx.x) >> 5;
    int nw   = (gridDim.x * blockDim.x) >> 5;
    float4 scA = d_scale1[ql * 2], scB = d_scale1[ql * 2 + 1];
    float4 shA = d_shift1[ql * 2], shB = d_shift1[ql * 2 + 1];
    float4 wgA = ((const float4*)Wg)[ql * 2], wgB = ((const float4*)Wg)[ql * 2 + 1];
    float bgv = bg[0];
    float sg = 0.f, sg2 = 0.f;
    for (int nd = wid; nd < n; nd += nw) {
        int r0 = d_rowptr[nd], r1 = d_rowptr[nd + 1];
        if (r0 == r1) continue;
        float4 bpA = d_Bp4[nd * 16 + ql * 2];
        float4 bpB = d_Bp4[nd * 16 + ql * 2 + 1];
        float4 oA = make_float4(fmaf(-bpA.x, scA.x, shA.x), fmaf(-bpA.y, scA.y, shA.y),
                                fmaf(-bpA.z, scA.z, shA.z), fmaf(-bpA.w, scA.w, shA.w));
        float4 oB = make_float4(fmaf(-bpB.x, scB.x, shB.x), fmaf(-bpB.y, scB.y, shB.y),
                                fmaf(-bpB.z, scB.z, shB.z), fmaf(-bpB.w, scB.w, shB.w));
        int j = r0;
        for (; j + 8 <= r1; j += 8) {
            int s0 = d_csrc[j + q];
            int s1 = d_csrc[j + 4 + q];
            uint4 raw0 = d_Ah[s0 * 8 + ql];
            uint4 raw1 = d_Ah[s1 * 8 + ql];
            float p0 = dot8(raw0, oA, oB, scA, scB, wgA, wgB);
            float p1 = dot8(raw1, oA, oB, scA, scB, wgA, wgB);
            #pragma unroll
            for (int off = 4; off; off >>= 1) {
                p0 += __shfl_xor_sync(0xffffffffu, p0, off);
                p1 += __shfl_xor_sync(0xffffffffu, p1, off);
            }
            if (ql == 0) {
                p0 += bgv; p1 += bgv;
                d_graw[j + q] = p0;
                d_graw[j + 4 + q] = p1;
                sg += p0 + p1;
                sg2 = fmaf(p0, p0, sg2);
                sg2 = fmaf(p1, p1, sg2);
            }
        }
        if (j + 4 <= r1) {
            int s = d_csrc[j + q];
            uint4 raw = d_Ah[s * 8 + ql];
            float p = dot8(raw, oA, oB, scA, scB, wgA, wgB);
            #pragma unroll
            for (int off = 4; off; off >>= 1)
                p += __shfl_xor_sync(0xffffffffu, p, off);
            if (ql == 0) {
                p += bgv;
                d_graw[j + q] = p;
                sg += p;
                sg2 = fmaf(p, p, sg2);
            }
            j += 4;
        }
        int rem = r1 - j;
        if (rem > 0) {
            bool act = (q < rem);
            int jj = j + (act ? q : 0);
            int s = d_csrc[jj];
            uint4 raw = d_Ah[s * 8 + ql];
            float p = dot8(raw, oA, oB, scA, scB, wgA, wgB);
            #pragma unroll
            for (int off = 4; off; off >>= 1)
                p += __shfl_xor_sync(0xffffffffu, p, off);
            if (ql == 0 && act) {
                p += bgv;
                d_graw[jj] = p;
                sg += p;
                sg2 = fmaf(p, p, sg2);
            }
        }
    }
    sg  += __shfl_xor_sync(0xffffffffu, sg, 8);
    sg2 += __shfl_xor_sync(0xffffffffu, sg2, 8);
    sg  += __shfl_xor_sync(0xffffffffu, sg, 16);
    sg2 += __shfl_xor_sync(0xffffffffu, sg2, 16);
    if (lane == 0) {
        atomicAdd(&d_gstats[0], sg);
        atomicAdd(&d_gstats[1], sg2);
    }
}

// ------------- K8 -------------
__global__ void k_bng(const float* __restrict__ gg, const float* __restrict__ bgb, float Ef) {
    float mu  = d_gstats[0] / Ef;
    float var = d_gstats[1] / Ef - mu * mu;
    float sc  = gg[0] * rsqrtf(var + BN_EPS);
    d_gparams[0] = sc;
    d_gparams[1] = bgb[0] - mu * sc;
}

// ------------- K9: fused softmax + aggregate, single sweep, in-lane weights -------------
__global__ void k_agg(float* __restrict__ out, int n) {
    int lane = threadIdx.x & 31;
    int q  = lane >> 3;
    int ql = lane & 7;
    int wid  = (blockIdx.x * blockDim.x + threadIdx.x) >> 5;
    int nw   = (gridDim.x * blockDim.x) >> 5;
    float4 scA = d_scale1[ql * 2], scB = d_scale1[ql * 2 + 1];
    float4 shA = d_shift1[ql * 2], shB = d_shift1[ql * 2 + 1];
    float gsc = d_gparams[0], gsh = d_gparams[1];
    float4* out4 = (float4*)out;
    for (int nd = wid; nd < n; nd += nw) {
        int r0 = d_rowptr[nd], r1 = d_rowptr[nd + 1];
        if (r0 == r1) {
            if (q == 0) {
                out4[nd * 16 + ql * 2]     = make_float4(0.f, 0.f, 0.f, 0.f);
                out4[nd * 16 + ql * 2 + 1] = make_float4(0.f, 0.f, 0.f, 0.f);
            }
            continue;
        }
        float4 bpA = d_Bp4[nd * 16 + ql * 2];
        float4 bpB = d_Bp4[nd * 16 + ql * 2 + 1];
        float4 oA = make_float4(fmaf(-bpA.x, scA.x, shA.x), fmaf(-bpA.y, scA.y, shA.y),
                                fmaf(-bpA.z, scA.z, shA.z), fmaf(-bpA.w, scA.w, shA.w));
        float4 oB = make_float4(fmaf(-bpB.x, scB.x, shB.x), fmaf(-bpB.y, scB.y, shB.y),
                                fmaf(-bpB.z, scB.z, shB.z), fmaf(-bpB.w, scB.w, shB.w));
        float4 accA = make_float4(0.f, 0.f, 0.f, 0.f);
        float4 accB = make_float4(0.f, 0.f, 0.f, 0.f);
        float ssum = 0.f;
        int j = r0;
        for (; j + 8 <= r1; j += 8) {
            int s0 = d_csrc[j + q];
            int s1 = d_csrc[j + 4 + q];
            float gr0 = d_graw[j + q];
            float gr1 = d_graw[j + 4 + q];
            uint4 raw0 = d_Ah[s0 * 8 + ql];
            uint4 raw1 = d_Ah[s1 * 8 + ql];
            float e0 = __expf(silu_f(fmaf(gr0, gsc, gsh)));
            float e1 = __expf(silu_f(fmaf(gr1, gsc, gsh)));
            ssum += e0 + e1;
            acc8(raw0, oA, oB, scA, scB, e0, accA, accB);
            acc8(raw1, oA, oB, scA, scB, e1, accA, accB);
        }
        if (j + 4 <= r1) {
            int s = d_csrc[j + q];
            float gr = d_graw[j + q];
            uint4 raw = d_Ah[s * 8 + ql];
            float e = __expf(silu_f(fmaf(gr, gsc, gsh)));
            ssum += e;
            acc8(raw, oA, oB, scA, scB, e, accA, accB);
            j += 4;
        }
        int rem = r1 - j;
        if (rem > 0) {
            bool act = (q < rem);
            int jj = j + (act ? q : 0);
            int s = d_csrc[jj];
            float gr = d_graw[jj];
            uint4 raw = d_Ah[s * 8 + ql];
            float e = act ? __expf(silu_f(fmaf(gr, gsc, gsh))) : 0.0f;
            ssum += e;
            acc8(raw, oA, oB, scA, scB, e, accA, accB);
        }
        ssum += __shfl_xor_sync(0xffffffffu, ssum, 8);
        ssum += __shfl_xor_sync(0xffffffffu, ssum, 16);
        float inv = 1.0f / (ssum + 1e-16f);
        #pragma unroll
        for (int off = 8; off <= 16; off <<= 1) {
            accA.x += __shfl_xor_sync(0xffffffffu, accA.x, off);
            accA.y += __shfl_xor_sync(0xffffffffu, accA.y, off);
            accA.z += __shfl_xor_sync(0xffffffffu, accA.z, off);
            accA.w += __shfl_xor_sync(0xffffffffu, accA.w, off);
            accB.x += __shfl_xor_sync(0xffffffffu, accB.x, off);
            accB.y += __shfl_xor_sync(0xffffffffu, accB.y, off);
            accB.z += __shfl_xor_sync(0xffffffffu, accB.z, off);
            accB.w += __shfl_xor_sync(0xffffffffu, accB.w, off);
        }
        if (q == 0) {
            out4[nd * 16 + ql * 2]     = make_float4(accA.x * inv, accA.y * inv,
                                                     accA.z * inv, accA.w * inv);
            out4[nd * 16 + ql * 2 + 1] = make_float4(accB.x * inv, accB.y * inv,
                                                     accB.z * inv, accB.w * inv);
        }
    }
}

// ------------- launch: two-stream DAG -------------
// main: init -> count(+V) -> scanA/B/C -> scatter ----\
//                                                       join -> gate -> bng -> agg
// side: node --------------(wait count)--> zstats -> bn1 /
extern "C" void kernel_launch(void* const* d_in, const int* in_sizes, int n_in,
                              void* d_out, int out_size) {
    const float* x   = (const float*)d_in[0];
    const float* pos = (const float*)d_in[1];
    const int*   ei  = (const int*)d_in[2];
    const float* W1  = (const float*)d_in[3];
    const float* b1  = (const float*)d_in[4];
    const float* g1  = (const float*)d_in[5];
    const float* be1 = (const float*)d_in[6];
    const float* Wg  = (const float*)d_in[7];
    const float* bg  = (const float*)d_in[8];
    const float* gg  = (const float*)d_in[9];
    const float* bgb = (const float*)d_in[10];
    float* out = (float*)d_out;

    int n = in_sizes[0] / INCH;   // 100000
    int e = in_sizes[2] / 2;      // 1600000
    int nb = (n + SCAN_BLK - 1) / SCAN_BLK;

    // fork side stream: k_node runs concurrent with init/count
    cudaEventRecord(g_fr.fork, 0);
    cudaStreamWaitEvent(g_fr.s, g_fr.fork, 0);
    k_node<<<512, 256, 0, g_fr.s>>>(x, pos, W1, n);

    // main chain: init + count (+V)
    k_init <<<256, 256>>>(n);
    k_count<<<512, 256>>>(ei, pos, e, n);
    cudaEventRecord(g_fr.ecnt, 0);

    // side chain: zstats + bn1 (needs node done [stream order] + count done [event])
    cudaStreamWaitEvent(g_fr.s, g_fr.ecnt, 0);
    k_zstats<<<1024, 256, 0, g_fr.s>>>(b1, W1, n);
    k_bn1   <<<1, 64, 0, g_fr.s>>>(g1, be1, b1, (float)e);
    cudaEventRecord(g_fr.join, g_fr.s);

    // main chain: scan + scatter (concurrent with zstats/bn1)
    k_scanA  <<<nb, SCAN_BLK>>>(n);
    k_scanB  <<<1, 128>>>(nb, n);
    k_scanC  <<<nb, SCAN_BLK>>>(n);
    k_scatter<<<512, 256>>>(ei, e, n);

    // join: gate needs bn1 params (side) + csrc (main)
    cudaStreamWaitEvent(0, g_fr.join, 0);

    k_gate<<<1024, 256>>>(Wg, bg, n);
    k_bng <<<1, 1>>>(gg, bgb, (float)e);
    k_agg <<<1024, 256>>>(out, n);
}

// round 15
// speedup vs baseline: 1.2019x; 1.2019x over previous
#include <cuda_runtime.h>
#include <cuda_fp16.h>
#include <math.h>

#define NMAXN 100000
#define NMAXE 1600000
#define INCH 61
#define OC 64
#define BN_EPS 1e-5f
#define SCAN_BLK 1024

// ------------- static device scratch (no allocation allowed) -------------
__device__ uint4  d_Ah[NMAXN * 8];    // 64 ch fp16 per node (128 B)
__device__ float4 d_Bp4[NMAXN * 16];  // pos @ W1[61:64], fp32
__device__ int    d_deg[NMAXN];
__device__ int    d_odeg[NMAXN];
__device__ float  d_V[NMAXN * 3];
__device__ int    d_scanned[NMAXN];
__device__ int    d_bsum[128];
__device__ int    d_rowptr[NMAXN + 1];
__device__ int    d_cursor[NMAXN];
__device__ int    d_csrc[NMAXE];
__device__ float  d_graw[NMAXE];
__device__ float  d_s1[OC];
__device__ float  d_s2[OC];
__device__ float  d_s3[OC];
__device__ float  d_s4[OC];
__device__ float  d_s5[OC];
__device__ float4 d_scale1[16];
__device__ float4 d_shift1[16];       // FOLDED: beta + (b1 - mu)*sc
__device__ float  d_gstats[2];
__device__ float  d_gparams[2];

// ------------- host-side streams/events for branched graph capture -------------
struct ForkResources {
    cudaStream_t s;
    cudaEvent_t  fork, ecnt, join;
    ForkResources() {
        cudaStreamCreateWithFlags(&s, cudaStreamNonBlocking);
        cudaEventCreateWithFlags(&fork, cudaEventDisableTiming);
        cudaEventCreateWithFlags(&ecnt, cudaEventDisableTiming);
        cudaEventCreateWithFlags(&join, cudaEventDisableTiming);
    }
};
static ForkResources g_fr;

__device__ __forceinline__ float silu_f(float t) {
    float u = 0.5f * t;
    float v;
    asm("tanh.approx.f32 %0, %1;" : "=f"(v) : "f"(u));
    return fmaf(u, v, u);
}

// dot over 8 channels: silu(fmaf(a, sc, o)) . wg
__device__ __forceinline__ float dot8(const uint4& raw,
                                      const float4& oA, const float4& oB,
                                      const float4& scA, const float4& scB,
                                      const float4& wgA, const float4& wgB) {
    const __half2* hp = (const __half2*)&raw;
    float2 a01 = __half22float2(hp[0]);
    float2 a23 = __half22float2(hp[1]);
    float2 a45 = __half22float2(hp[2]);
    float2 a67 = __half22float2(hp[3]);
    return silu_f(fmaf(a01.x, scA.x, oA.x)) * wgA.x
         + silu_f(fmaf(a01.y, scA.y, oA.y)) * wgA.y
         + silu_f(fmaf(a23.x, scA.z, oA.z)) * wgA.z
         + silu_f(fmaf(a23.y, scA.w, oA.w)) * wgA.w
         + silu_f(fmaf(a45.x, scB.x, oB.x)) * wgB.x
         + silu_f(fmaf(a45.y, scB.y, oB.y)) * wgB.y
         + silu_f(fmaf(a67.x, scB.z, oB.z)) * wgB.z
         + silu_f(fmaf(a67.y, scB.w, oB.w)) * wgB.w;
}

// accA/accB += w * silu(fmaf(a, sc, o)) over 8 channels
__device__ __forceinline__ void acc8(const uint4& raw,
                                     const float4& oA, const float4& oB,
                                     const float4& scA, const float4& scB,
                                     float w, float4& accA, float4& accB) {
    const __half2* hp = (const __half2*)&raw;
    float2 a01 = __half22float2(hp[0]);
    float2 a23 = __half22float2(hp[1]);
    float2 a45 = __half22float2(hp[2]);
    float2 a67 = __half22float2(hp[3]);
    accA.x = fmaf(w, silu_f(fmaf(a01.x, scA.x, oA.x)), accA.x);
    accA.y = fmaf(w, silu_f(fmaf(a01.y, scA.y, oA.y)), accA.y);
    accA.z = fmaf(w, silu_f(fmaf(a23.x, scA.z, oA.z)), accA.z);
    accA.w = fmaf(w, silu_f(fmaf(a23.y, scA.w, oA.w)), accA.w);
    accB.x = fmaf(w, silu_f(fmaf(a45.x, scB.x, oB.x)), accB.x);
    accB.y = fmaf(w, silu_f(fmaf(a45.y, scB.y, oB.y)), accB.y);
    accB.z = fmaf(w, silu_f(fmaf(a67.x, scB.z, oB.z)), accB.z);
    accB.w = fmaf(w, silu_f(fmaf(a67.y, scB.w, oB.w)), accB.w);
}

// ------------- K0 -------------
__global__ void k_init(int n) {
    int i = blockIdx.x * blockDim.x + threadIdx.x;
    int st = gridDim.x * blockDim.x;
    for (int t = i; t < n; t += st) { d_deg[t] = 0; d_odeg[t] = 0; }
    for (int t = i; t < 3 * n; t += st) d_V[t] = 0.f;
    if (i < OC) { d_s1[i] = 0.f; d_s2[i] = 0.f; d_s3[i] = 0.f; d_s4[i] = 0.f; d_s5[i] = 0.f; }
    if (i < 2)  { d_gstats[i] = 0.f; }
}

// ------------- K1: per-node transform -------------
__global__ void k_node(const float* __restrict__ x, const float* __restrict__ pos,
                       const float* __restrict__ W1, int n) {
    __shared__ float2 sW[64 * 32];
    const float2* W2 = (const float2*)W1;
    for (int i = threadIdx.x; i < 64 * 32; i += blockDim.x) sW[i] = W2[i];
    __syncthreads();
    int lane = threadIdx.x & 31;
    int wid  = (blockIdx.x * blockDim.x + threadIdx.x) >> 5;
    int nw   = (gridDim.x * blockDim.x) >> 5;
    __half2* Ah2 = (__half2*)d_Ah;
    float2*  Bp2 = (float2*)d_Bp4;
    for (int nd = wid; nd < n; nd += nw) {
        float a0 = 0.f, a1 = 0.f, b0 = 0.f, b1v = 0.f;
        const float* xr = x + (long long)nd * INCH;
        #pragma unroll
        for (int k = 0; k < INCH; k++) {
            float xv = __ldg(xr + k);
            float2 w = sW[k * 32 + lane];
            a0 = fmaf(xv, w.x, a0);
            a1 = fmaf(xv, w.y, a1);
        }
        const float* pr = pos + (long long)nd * 3;
        #pragma unroll
        for (int k = 0; k < 3; k++) {
            float pv = __ldg(pr + k);
            float2 w = sW[(INCH + k) * 32 + lane];
            b0  = fmaf(pv, w.x, b0);
            b1v = fmaf(pv, w.y, b1v);
        }
        Ah2[nd * 32 + lane] = __floats2half2_rn(a0 + b0, a1 + b1v);
        Bp2[nd * 32 + lane] = make_float2(b0, b1v);
    }
}

// ------------- K2: degree histograms + V accumulation -------------
__global__ void k_count(const int* __restrict__ ei, const float* __restrict__ pos,
                        int e, int n) {
    int i = blockIdx.x * blockDim.x + threadIdx.x;
    int st = gridDim.x * blockDim.x;
    for (; i < e; i += st) {
        unsigned s = (unsigned)ei[i];
        unsigned d = (unsigned)ei[e + i];
        if (s >= (unsigned)n || d >= (unsigned)n) continue;
        atomicAdd(&d_deg[d], 1);
        atomicAdd(&d_odeg[s], 1);
        const float* pd = pos + (size_t)d * 3;
        atomicAdd(&d_V[s * 3 + 0], pd[0]);
        atomicAdd(&d_V[s * 3 + 1], pd[1]);
        atomicAdd(&d_V[s * 3 + 2], pd[2]);
    }
}

// ------------- K3a -------------
__global__ void k_scanA(int n) {
    __shared__ int sh[32];
    int t = threadIdx.x, lane = t & 31, w = t >> 5;
    int idx = blockIdx.x * SCAN_BLK + t;
    int v = (idx < n) ? d_deg[idx] : 0;
    int xv = v;
    #pragma unroll
    for (int off = 1; off < 32; off <<= 1) {
        int y = __shfl_up_sync(0xffffffffu, xv, off);
        if (lane >= off) xv += y;
    }
    if (lane == 31) sh[w] = xv;
    __syncthreads();
    if (w == 0) {
        int y2 = sh[lane];
        #pragma unroll
        for (int off = 1; off < 32; off <<= 1) {
            int z = __shfl_up_sync(0xffffffffu, y2, off);
            if (lane >= off) y2 += z;
        }
        sh[lane] = y2;
    }
    __syncthreads();
    int incl = xv + ((w > 0) ? sh[w - 1] : 0);
    if (idx < n) d_scanned[idx] = incl;
    if (t == SCAN_BLK - 1) d_bsum[blockIdx.x] = incl;
}

// ------------- K3b -------------
__global__ void k_scanB(int nb, int n) {
    __shared__ int sw[4];
    int t = threadIdx.x, lane = t & 31, w = t >> 5;
    int v = (t < nb) ? d_bsum[t] : 0;
    int xv = v;
    #pragma unroll
    for (int off = 1; off < 32; off <<= 1) {
        int y = __shfl_up_sync(0xffffffffu, xv, off);
        if (lane >= off) xv += y;
    }
    if (lane == 31) sw[w] = xv;
    __syncthreads();
    if (t == 0) {
        int run = 0;
        #pragma unroll
        for (int i = 0; i < 4; i++) { int tmp = sw[i]; sw[i] = run; run += tmp; }
    }
    __syncthreads();
    int incl = xv + sw[w];
    if (t < nb) d_bsum[t] = incl - v;
    if (t == nb - 1) d_rowptr[n] = incl;
}

// ------------- K3c -------------
__global__ void k_scanC(int n) {
    int idx = blockIdx.x * SCAN_BLK + threadIdx.x;
    if (idx < n) {
        int ex = d_scanned[idx] - d_deg[idx] + d_bsum[blockIdx.x];
        d_rowptr[idx] = ex;
        d_cursor[idx] = ex;
    }
}

// ------------- K4: scatter src ids into CSR slots -------------
__global__ void k_scatter(const int* __restrict__ ei, int e, int n) {
    int i = blockIdx.x * blockDim.x + threadIdx.x;
    int st = gridDim.x * blockDim.x;
    for (; i < e; i += st) {
        unsigned s = (unsigned)ei[i];
        unsigned d = (unsigned)ei[e + i];
        if (s >= (unsigned)n || d >= (unsigned)n) continue;
        int p = atomicAdd(&d_cursor[d], 1);
        d_csrc[p] = (int)s;
    }
}

// ------------- K5: node-level BN1 stats (1-node loop; moderate grid) -------------
__global__ void k_zstats(const float* __restrict__ b1, const float* __restrict__ W1, int n) {
    int lane = threadIdx.x & 31;
    int wid  = (blockIdx.x * blockDim.x + threadIdx.x) >> 5;
    int nw   = (gridDim.x * blockDim.x) >> 5;
    const __half2* Ah2 = (const __half2*)d_Ah;
    const float2*  Bp2 = (const float2*)d_Bp4;
    float2 bias = ((const float2*)b1)[lane];
    float2 w61 = ((const float2*)(W1 + 61 * OC))[lane];
    float2 w62 = ((const float2*)(W1 + 62 * OC))[lane];
    float2 w63 = ((const float2*)(W1 + 63 * OC))[lane];
    float s1x = 0.f, s1y = 0.f, s2x = 0.f, s2y = 0.f, s3x = 0.f, s3y = 0.f;
    float s4x = 0.f, s4y = 0.f, s5x = 0.f, s5y = 0.f;
    for (int nd = wid; nd < n; nd += nw) {
        float od = (float)d_odeg[nd];
        float id = (float)d_deg[nd];
        float2 a  = __half22float2(Ah2[nd * 32 + lane]);
        float2 bp = Bp2[nd * 32 + lane];
        float v0 = d_V[nd * 3 + 0], v1 = d_V[nd * 3 + 1], v2 = d_V[nd * 3 + 2];
        s1x = fmaf(od, a.x, s1x);          s1y = fmaf(od, a.y, s1y);
        s2x = fmaf(id, bp.x, s2x);         s2y = fmaf(id, bp.y, s2y);
        s3x = fmaf(od * a.x, a.x, s3x);    s3y = fmaf(od * a.y, a.y, s3y);
        float ox = bias.x - bp.x, oy = bias.y - bp.y;
        s4x = fmaf(id * ox, ox, s4x);      s4y = fmaf(id * oy, oy, s4y);
        float bvx = v0 * w61.x + v1 * w62.x + v2 * w63.x;
        float bvy = v0 * w61.y + v1 * w62.y + v2 * w63.y;
        s5x = fmaf(a.x, bvx, s5x);         s5y = fmaf(a.y, bvy, s5y);
    }
    atomicAdd(&d_s1[2 * lane], s1x);     atomicAdd(&d_s1[2 * lane + 1], s1y);
    atomicAdd(&d_s2[2 * lane], s2x);     atomicAdd(&d_s2[2 * lane + 1], s2y);
    atomicAdd(&d_s3[2 * lane], s3x);     atomicAdd(&d_s3[2 * lane + 1], s3y);
    atomicAdd(&d_s4[2 * lane], s4x);     atomicAdd(&d_s4[2 * lane + 1], s4y);
    atomicAdd(&d_s5[2 * lane], s5x);     atomicAdd(&d_s5[2 * lane + 1], s5y);
}

// ------------- K6: finalize BN1 params (b1 folded into shift) -------------
__global__ void k_bn1(const float* __restrict__ g1, const float* __restrict__ be1,
                      const float* __restrict__ b1, float Ef) {
    int c = threadIdx.x;
    float bc = b1[c];
    float sumz  = d_s1[c] + Ef * bc - d_s2[c];
    float sumz2 = d_s3[c] + d_s4[c] + 2.0f * (bc * d_s1[c] - d_s5[c]);
    float mu  = sumz / Ef;
    float var = sumz2 / Ef - mu * mu;
    float sc  = g1[c] * rsqrtf(var + BN_EPS);
    ((float*)d_scale1)[c] = sc;
    ((float*)d_shift1)[c] = be1[c] + (bc - mu) * sc;
}

// ------------- K7: gate (quarter-warp per edge, 8 edges/iter) -------------
__global__ void k_gate(const float* __restrict__ Wg, const float* __restrict__ bg, int n) {
    int lane = threadIdx.x & 31;
    int q  = lane >> 3;
    int ql = lane & 7;
    int wid  = (blockIdx.x * blockDim.x + threadIdx.x) >> 5;
    int nw   = (gridDim.x * blockDim.x) >> 5;
    float4 scA = d_scale1[ql * 2], scB = d_scale1[ql * 2 + 1];
    float4 shA = d_shift1[ql * 2], shB = d_shift1[ql * 2 + 1];
    float4 wgA = ((const float4*)Wg)[ql * 2], wgB = ((const float4*)Wg)[ql * 2 + 1];
    float bgv = bg[0];
    float sg = 0.f, sg2 = 0.f;
    for (int nd = wid; nd < n; nd += nw) {
        int r0 = d_rowptr[nd], r1 = d_rowptr[nd + 1];
        if (r0 == r1) continue;
        float4 bpA = d_Bp4[nd * 16 + ql * 2];
        float4 bpB = d_Bp4[nd * 16 + ql * 2 + 1];
        float4 oA = make_float4(fmaf(-bpA.x, scA.x, shA.x), fmaf(-bpA.y, scA.y, shA.y),
                                fmaf(-bpA.z, scA.z, shA.z), fmaf(-bpA.w, scA.w, shA.w));
        float4 oB = make_float4(fmaf(-bpB.x, scB.x, shB.x), fmaf(-bpB.y, scB.y, shB.y),
                                fmaf(-bpB.z, scB.z, shB.z), fmaf(-bpB.w, scB.w, shB.w));
        int j = r0;
        for (; j + 8 <= r1; j += 8) {
            int s0 = d_csrc[j + q];
            int s1 = d_csrc[j + 4 + q];
            uint4 raw0 = d_Ah[s0 * 8 + ql];
            uint4 raw1 = d_Ah[s1 * 8 + ql];
            float p0 = dot8(raw0, oA, oB, scA, scB, wgA, wgB);
            float p1 = dot8(raw1, oA, oB, scA, scB, wgA, wgB);
            #pragma unroll
            for (int off = 4; off; off >>= 1) {
                p0 += __shfl_xor_sync(0xffffffffu, p0, off);
                p1 += __shfl_xor_sync(0xffffffffu, p1, off);
            }
            if (ql == 0) {
                p0 += bgv; p1 += bgv;
                d_graw[j + q] = p0;
                d_graw[j + 4 + q] = p1;
                sg += p0 + p1;
                sg2 = fmaf(p0, p0, sg2);
                sg2 = fmaf(p1, p1, sg2);
            }
        }
        if (j + 4 <= r1) {
            int s = d_csrc[j + q];
            uint4 raw = d_Ah[s * 8 + ql];
            float p = dot8(raw, oA, oB, scA, scB, wgA, wgB);
            #pragma unroll
            for (int off = 4; off; off >>= 1)
                p += __shfl_xor_sync(0xffffffffu, p, off);
            if (ql == 0) {
                p += bgv;
                d_graw[j + q] = p;
                sg += p;
                sg2 = fmaf(p, p, sg2);
            }
            j += 4;
        }
        int rem = r1 - j;
        if (rem > 0) {
            bool act = (q < rem);
            int jj = j + (act ? q : 0);
            int s = d_csrc[jj];
            uint4 raw = d_Ah[s * 8 + ql];
            float p = dot8(raw, oA, oB, scA, scB, wgA, wgB);
            #pragma unroll
            for (int off = 4; off; off >>= 1)
                p += __shfl_xor_sync(0xffffffffu, p, off);
            if (ql == 0 && act) {
                p += bgv;
                d_graw[jj] = p;
                sg += p;
                sg2 = fmaf(p, p, sg2);
            }
        }
    }
    sg  += __shfl_xor_sync(0xffffffffu, sg, 8);
    sg2 += __shfl_xor_sync(0xffffffffu, sg2, 8);
    sg  += __shfl_xor_sync(0xffffffffu, sg, 16);
    sg2 += __shfl_xor_sync(0xffffffffu, sg2, 16);
    if (lane == 0) {
        atomicAdd(&d_gstats[0], sg);
        atomicAdd(&d_gstats[1], sg2);
    }
}

// ------------- K8 -------------
__global__ void k_bng(const float* __restrict__ gg, const float* __restrict__ bgb, float Ef) {
    float mu  = d_gstats[0] / Ef;
    float var = d_gstats[1] / Ef - mu * mu;
    float sc  = gg[0] * rsqrtf(var + BN_EPS);
    d_gparams[0] = sc;
    d_gparams[1] = bgb[0] - mu * sc;
}

// ------------- K9: fused softmax + aggregate, single sweep, in-lane weights -------------
__global__ void k_agg(float* __restrict__ out, int n) {
    int lane = threadIdx.x & 31;
    int q  = lane >> 3;
    int ql = lane & 7;
    int wid  = (blockIdx.x * blockDim.x + threadIdx.x) >> 5;
    int nw   = (gridDim.x * blockDim.x) >> 5;
    float4 scA = d_scale1[ql * 2], scB = d_scale1[ql * 2 + 1];
    float4 shA = d_shift1[ql * 2], shB = d_shift1[ql * 2 + 1];
    float gsc = d_gparams[0], gsh = d_gparams[1];
    float4* out4 = (float4*)out;
    for (int nd = wid; nd < n; nd += nw) {
        int r0 = d_rowptr[nd], r1 = d_rowptr[nd + 1];
        if (r0 == r1) {
            if (q == 0) {
                out4[nd * 16 + ql * 2]     = make_float4(0.f, 0.f, 0.f, 0.f);
                out4[nd * 16 + ql * 2 + 1] = make_float4(0.f, 0.f, 0.f, 0.f);
            }
            continue;
        }
        float4 bpA = d_Bp4[nd * 16 + ql * 2];
        float4 bpB = d_Bp4[nd * 16 + ql * 2 + 1];
        float4 oA = make_float4(fmaf(-bpA.x, scA.x, shA.x), fmaf(-bpA.y, scA.y, shA.y),
                                fmaf(-bpA.z, scA.z, shA.z), fmaf(-bpA.w, scA.w, shA.w));
        float4 oB = make_float4(fmaf(-bpB.x, scB.x, shB.x), fmaf(-bpB.y, scB.y, shB.y),
                                fmaf(-bpB.z, scB.z, shB.z), fmaf(-bpB.w, scB.w, shB.w));
        float4 accA = make_float4(0.f, 0.f, 0.f, 0.f);
        float4 accB = make_float4(0.f, 0.f, 0.f, 0.f);
        float ssum = 0.f;
        int j = r0;
        for (; j + 8 <= r1; j += 8) {
            int s0 = d_csrc[j + q];
            int s1 = d_csrc[j + 4 + q];
            float gr0 = d_graw[j + q];
            float gr1 = d_graw[j + 4 + q];
            uint4 raw0 = d_Ah[s0 * 8 + ql];
            uint4 raw1 = d_Ah[s1 * 8 + ql];
            float e0 = __expf(silu_f(fmaf(gr0, gsc, gsh)));
            float e1 = __expf(silu_f(fmaf(gr1, gsc, gsh)));
            ssum += e0 + e1;
            acc8(raw0, oA, oB, scA, scB, e0, accA, accB);
            acc8(raw1, oA, oB, scA, scB, e1, accA, accB);
        }
        if (j + 4 <= r1) {
            int s = d_csrc[j + q];
            float gr = d_graw[j + q];
            uint4 raw = d_Ah[s * 8 + ql];
            float e = __expf(silu_f(fmaf(gr, gsc, gsh)));
            ssum += e;
            acc8(raw, oA, oB, scA, scB, e, accA, accB);
            j += 4;
        }
        int rem = r1 - j;
        if (rem > 0) {
            bool act = (q < rem);
            int jj = j + (act ? q : 0);
            int s = d_csrc[jj];
            float gr = d_graw[jj];
            uint4 raw = d_Ah[s * 8 + ql];
            float e = act ? __expf(silu_f(fmaf(gr, gsc, gsh))) : 0.0f;
            ssum += e;
            acc8(raw, oA, oB, scA, scB, e, accA, accB);
        }
        ssum += __shfl_xor_sync(0xffffffffu, ssum, 8);
        ssum += __shfl_xor_sync(0xffffffffu, ssum, 16);
        float inv = 1.0f / (ssum + 1e-16f);
        #pragma unroll
        for (int off = 8; off <= 16; off <<= 1) {
            accA.x += __shfl_xor_sync(0xffffffffu, accA.x, off);
            accA.y += __shfl_xor_sync(0xffffffffu, accA.y, off);
            accA.z += __shfl_xor_sync(0xffffffffu, accA.z, off);
            accA.w += __shfl_xor_sync(0xffffffffu, accA.w, off);
            accB.x += __shfl_xor_sync(0xffffffffu, accB.x, off);
            accB.y += __shfl_xor_sync(0xffffffffu, accB.y, off);
            accB.z += __shfl_xor_sync(0xffffffffu, accB.z, off);
            accB.w += __shfl_xor_sync(0xffffffffu, accB.w, off);
        }
        if (q == 0) {
            out4[nd * 16 + ql * 2]     = make_float4(accA.x * inv, accA.y * inv,
                                                     accA.z * inv, accA.w * inv);
            out4[nd * 16 + ql * 2 + 1] = make_float4(accB.x * inv, accB.y * inv,
                                                     accB.z * inv, accB.w * inv);
        }
    }
}

// ------------- launch: two-stream DAG -------------
// main: init -> count(+V) -> scanA/B/C -> scatter ----\
//                                                       join -> gate -> bng -> agg
// side: node --------------(wait count)--> zstats -> bn1 /
extern "C" void kernel_launch(void* const* d_in, const int* in_sizes, int n_in,
                              void* d_out, int out_size) {
    const float* x   = (const float*)d_in[0];
    const float* pos = (const float*)d_in[1];
    const int*   ei  = (const int*)d_in[2];
    const float* W1  = (const float*)d_in[3];
    const float* b1  = (const float*)d_in[4];
    const float* g1  = (const float*)d_in[5];
    const float* be1 = (const float*)d_in[6];
    const float* Wg  = (const float*)d_in[7];
    const float* bg  = (const float*)d_in[8];
    const float* gg  = (const float*)d_in[9];
    const float* bgb = (const float*)d_in[10];
    float* out = (float*)d_out;

    int n = in_sizes[0] / INCH;   // 100000
    int e = in_sizes[2] / 2;      // 1600000
    int nb = (n + SCAN_BLK - 1) / SCAN_BLK;

    // fork side stream: k_node runs concurrent with init/count
    cudaEventRecord(g_fr.fork, 0);
    cudaStreamWaitEvent(g_fr.s, g_fr.fork, 0);
    k_node<<<512, 256, 0, g_fr.s>>>(x, pos, W1, n);

    // main chain: init + count (+V)
    k_init <<<256, 256>>>(n);
    k_count<<<512, 256>>>(ei, pos, e, n);
    cudaEventRecord(g_fr.ecnt, 0);

    // side chain: zstats + bn1 (needs node done [stream order] + count done [event])
    cudaStreamWaitEvent(g_fr.s, g_fr.ecnt, 0);
    k_zstats<<<512, 256, 0, g_fr.s>>>(b1, W1, n);
    k_bn1   <<<1, 64, 0, g_fr.s>>>(g1, be1, b1, (float)e);
    cudaEventRecord(g_fr.join, g_fr.s);

    // main chain: scan + scatter (concurrent with zstats/bn1)
    k_scanA  <<<nb, SCAN_BLK>>>(n);
    k_scanB  <<<1, 128>>>(nb, n);
    k_scanC  <<<nb, SCAN_BLK>>>(n);
    k_scatter<<<512, 256>>>(ei, e, n);

    // join: gate needs bn1 params (side) + csrc (main)
    cudaStreamWaitEvent(0, g_fr.join, 0);

    k_gate<<<1024, 256>>>(Wg, bg, n);
    k_bng <<<1, 1>>>(gg, bgb, (float)e);
    k_agg <<<1024, 256>>>(out, n);
}

// round 16
// speedup vs baseline: 1.3246x; 1.1021x over previous
#include <cuda_runtime.h>
#include <cuda_fp16.h>
#include <math.h>

#define NMAXN 100000
#define NMAXE 1600000
#define INCH 61
#define OC 64
#define BN_EPS 1e-5f
#define SCAN_BLK 1024

// ------------- static device scratch (no allocation allowed) -------------
__device__ uint4  d_Ah[NMAXN * 8];    // 64 ch fp16 per node (128 B)
__device__ float4 d_Bp4[NMAXN * 16];  // pos @ W1[61:64], fp32
__device__ int    d_deg[NMAXN];
__device__ int    d_odeg[NMAXN];
__device__ float  d_V[NMAXN * 3];
__device__ int    d_scanned[NMAXN];
__device__ int    d_bsum[128];
__device__ int    d_rowptr[NMAXN + 1];
__device__ int    d_cursor[NMAXN];
__device__ int    d_csrc[NMAXE];
__device__ float  d_graw[NMAXE];
__device__ float  d_s1[OC];
__device__ float  d_s2[OC];
__device__ float  d_s3[OC];
__device__ float  d_s4[OC];
__device__ float  d_s5[OC];
__device__ float4 d_scale1[16];
__device__ float4 d_shift1[16];       // FOLDED: beta + (b1 - mu)*sc
__device__ float  d_gstats[2];
__device__ float  d_gparams[2];

// ------------- host-side streams/events for branched graph capture -------------
struct ForkResources {
    cudaStream_t s;
    cudaEvent_t  fork, ecnt, join;
    ForkResources() {
        cudaStreamCreateWithFlags(&s, cudaStreamNonBlocking);
        cudaEventCreateWithFlags(&fork, cudaEventDisableTiming);
        cudaEventCreateWithFlags(&ecnt, cudaEventDisableTiming);
        cudaEventCreateWithFlags(&join, cudaEventDisableTiming);
    }
};
static ForkResources g_fr;

__device__ __forceinline__ float silu_f(float t) {
    float u = 0.5f * t;
    float v;
    asm("tanh.approx.f32 %0, %1;" : "=f"(v) : "f"(u));
    return fmaf(u, v, u);
}

// dot over 8 channels: silu(fmaf(a, sc, o)) . wg
__device__ __forceinline__ float dot8(const uint4& raw,
                                      const float4& oA, const float4& oB,
                                      const float4& scA, const float4& scB,
                                      const float4& wgA, const float4& wgB) {
    const __half2* hp = (const __half2*)&raw;
    float2 a01 = __half22float2(hp[0]);
    float2 a23 = __half22float2(hp[1]);
    float2 a45 = __half22float2(hp[2]);
    float2 a67 = __half22float2(hp[3]);
    return silu_f(fmaf(a01.x, scA.x, oA.x)) * wgA.x
         + silu_f(fmaf(a01.y, scA.y, oA.y)) * wgA.y
         + silu_f(fmaf(a23.x, scA.z, oA.z)) * wgA.z
         + silu_f(fmaf(a23.y, scA.w, oA.w)) * wgA.w
         + silu_f(fmaf(a45.x, scB.x, oB.x)) * wgB.x
         + silu_f(fmaf(a45.y, scB.y, oB.y)) * wgB.y
         + silu_f(fmaf(a67.x, scB.z, oB.z)) * wgB.z
         + silu_f(fmaf(a67.y, scB.w, oB.w)) * wgB.w;
}

// accA/accB += w * silu(fmaf(a, sc, o)) over 8 channels
__device__ __forceinline__ void acc8(const uint4& raw,
                                     const float4& oA, const float4& oB,
                                     const float4& scA, const float4& scB,
                                     float w, float4& accA, float4& accB) {
    const __half2* hp = (const __half2*)&raw;
    float2 a01 = __half22float2(hp[0]);
    float2 a23 = __half22float2(hp[1]);
    float2 a45 = __half22float2(hp[2]);
    float2 a67 = __half22float2(hp[3]);
    accA.x = fmaf(w, silu_f(fmaf(a01.x, scA.x, oA.x)), accA.x);
    accA.y = fmaf(w, silu_f(fmaf(a01.y, scA.y, oA.y)), accA.y);
    accA.z = fmaf(w, silu_f(fmaf(a23.x, scA.z, oA.z)), accA.z);
    accA.w = fmaf(w, silu_f(fmaf(a23.y, scA.w, oA.w)), accA.w);
    accB.x = fmaf(w, silu_f(fmaf(a45.x, scB.x, oB.x)), accB.x);
    accB.y = fmaf(w, silu_f(fmaf(a45.y, scB.y, oB.y)), accB.y);
    accB.z = fmaf(w, silu_f(fmaf(a67.x, scB.z, oB.z)), accB.z);
    accB.w = fmaf(w, silu_f(fmaf(a67.y, scB.w, oB.w)), accB.w);
}

// ------------- K0 -------------
__global__ void k_init(int n) {
    int i = blockIdx.x * blockDim.x + threadIdx.x;
    int st = gridDim.x * blockDim.x;
    for (int t = i; t < n; t += st) { d_deg[t] = 0; d_odeg[t] = 0; }
    for (int t = i; t < 3 * n; t += st) d_V[t] = 0.f;
    if (i < OC) { d_s1[i] = 0.f; d_s2[i] = 0.f; d_s3[i] = 0.f; d_s4[i] = 0.f; d_s5[i] = 0.f; }
    if (i < 2)  { d_gstats[i] = 0.f; }
}

// ------------- K1: per-node transform -------------
__global__ void k_node(const float* __restrict__ x, const float* __restrict__ pos,
                       const float* __restrict__ W1, int n) {
    __shared__ float2 sW[64 * 32];
    const float2* W2 = (const float2*)W1;
    for (int i = threadIdx.x; i < 64 * 32; i += blockDim.x) sW[i] = W2[i];
    __syncthreads();
    int lane = threadIdx.x & 31;
    int wid  = (blockIdx.x * blockDim.x + threadIdx.x) >> 5;
    int nw   = (gridDim.x * blockDim.x) >> 5;
    __half2* Ah2 = (__half2*)d_Ah;
    float2*  Bp2 = (float2*)d_Bp4;
    for (int nd = wid; nd < n; nd += nw) {
        float a0 = 0.f, a1 = 0.f, b0 = 0.f, b1v = 0.f;
        const float* xr = x + (long long)nd * INCH;
        #pragma unroll
        for (int k = 0; k < INCH; k++) {
            float xv = __ldg(xr + k);
            float2 w = sW[k * 32 + lane];
            a0 = fmaf(xv, w.x, a0);
            a1 = fmaf(xv, w.y, a1);
        }
        const float* pr = pos + (long long)nd * 3;
        #pragma unroll
        for (int k = 0; k < 3; k++) {
            float pv = __ldg(pr + k);
            float2 w = sW[(INCH + k) * 32 + lane];
            b0  = fmaf(pv, w.x, b0);
            b1v = fmaf(pv, w.y, b1v);
        }
        Ah2[nd * 32 + lane] = __floats2half2_rn(a0 + b0, a1 + b1v);
        Bp2[nd * 32 + lane] = make_float2(b0, b1v);
    }
}

// ------------- K2: degree histograms + V accumulation -------------
__global__ void k_count(const int* __restrict__ ei, const float* __restrict__ pos,
                        int e, int n) {
    int i = blockIdx.x * blockDim.x + threadIdx.x;
    int st = gridDim.x * blockDim.x;
    for (; i < e; i += st) {
        unsigned s = (unsigned)ei[i];
        unsigned d = (unsigned)ei[e + i];
        if (s >= (unsigned)n || d >= (unsigned)n) continue;
        atomicAdd(&d_deg[d], 1);
        atomicAdd(&d_odeg[s], 1);
        const float* pd = pos + (size_t)d * 3;
        atomicAdd(&d_V[s * 3 + 0], pd[0]);
        atomicAdd(&d_V[s * 3 + 1], pd[1]);
        atomicAdd(&d_V[s * 3 + 2], pd[2]);
    }
}

// ------------- K3a -------------
__global__ void k_scanA(int n) {
    __shared__ int sh[32];
    int t = threadIdx.x, lane = t & 31, w = t >> 5;
    int idx = blockIdx.x * SCAN_BLK + t;
    int v = (idx < n) ? d_deg[idx] : 0;
    int xv = v;
    #pragma unroll
    for (int off = 1; off < 32; off <<= 1) {
        int y = __shfl_up_sync(0xffffffffu, xv, off);
        if (lane >= off) xv += y;
    }
    if (lane == 31) sh[w] = xv;
    __syncthreads();
    if (w == 0) {
        int y2 = sh[lane];
        #pragma unroll
        for (int off = 1; off < 32; off <<= 1) {
            int z = __shfl_up_sync(0xffffffffu, y2, off);
            if (lane >= off) y2 += z;
        }
        sh[lane] = y2;
    }
    __syncthreads();
    int incl = xv + ((w > 0) ? sh[w - 1] : 0);
    if (idx < n) d_scanned[idx] = incl;
    if (t == SCAN_BLK - 1) d_bsum[blockIdx.x] = incl;
}

// ------------- K3b -------------
__global__ void k_scanB(int nb, int n) {
    __shared__ int sw[4];
    int t = threadIdx.x, lane = t & 31, w = t >> 5;
    int v = (t < nb) ? d_bsum[t] : 0;
    int xv = v;
    #pragma unroll
    for (int off = 1; off < 32; off <<= 1) {
        int y = __shfl_up_sync(0xffffffffu, xv, off);
        if (lane >= off) xv += y;
    }
    if (lane == 31) sw[w] = xv;
    __syncthreads();
    if (t == 0) {
        int run = 0;
        #pragma unroll
        for (int i = 0; i < 4; i++) { int tmp = sw[i]; sw[i] = run; run += tmp; }
    }
    __syncthreads();
    int incl = xv + sw[w];
    if (t < nb) d_bsum[t] = incl - v;
    if (t == nb - 1) d_rowptr[n] = incl;
}

// ------------- K3c -------------
__global__ void k_scanC(int n) {
    int idx = blockIdx.x * SCAN_BLK + threadIdx.x;
    if (idx < n) {
        int ex = d_scanned[idx] - d_deg[idx] + d_bsum[blockIdx.x];
        d_rowptr[idx] = ex;
        d_cursor[idx] = ex;
    }
}

// ------------- K4: scatter src ids into CSR slots -------------
__global__ void k_scatter(const int* __restrict__ ei, int e, int n) {
    int i = blockIdx.x * blockDim.x + threadIdx.x;
    int st = gridDim.x * blockDim.x;
    for (; i < e; i += st) {
        unsigned s = (unsigned)ei[i];
        unsigned d = (unsigned)ei[e + i];
        if (s >= (unsigned)n || d >= (unsigned)n) continue;
        int p = atomicAdd(&d_cursor[d], 1);
        d_csrc[p] = (int)s;
    }
}

// ------------- K5: node-level BN1 stats (grid 256, 2-node ILP) -------------
__global__ void k_zstats(const float* __restrict__ b1, const float* __restrict__ W1, int n) {
    int lane = threadIdx.x & 31;
    int wid  = (blockIdx.x * blockDim.x + threadIdx.x) >> 5;
    int nw   = (gridDim.x * blockDim.x) >> 5;
    const __half2* Ah2 = (const __half2*)d_Ah;
    const float2*  Bp2 = (const float2*)d_Bp4;
    float2 bias = ((const float2*)b1)[lane];
    float2 w61 = ((const float2*)(W1 + 61 * OC))[lane];
    float2 w62 = ((const float2*)(W1 + 62 * OC))[lane];
    float2 w63 = ((const float2*)(W1 + 63 * OC))[lane];
    float s1x = 0.f, s1y = 0.f, s2x = 0.f, s2y = 0.f, s3x = 0.f, s3y = 0.f;
    float s4x = 0.f, s4y = 0.f, s5x = 0.f, s5y = 0.f;
    int nd = wid;
    for (; nd + nw < n; nd += 2 * nw) {
        int nd2 = nd + nw;
        float odA = (float)d_odeg[nd],  odB = (float)d_odeg[nd2];
        float idA = (float)d_deg[nd],   idB = (float)d_deg[nd2];
        float2 aA  = __half22float2(Ah2[nd * 32 + lane]);
        float2 aB  = __half22float2(Ah2[nd2 * 32 + lane]);
        float2 bpA = Bp2[nd * 32 + lane];
        float2 bpB = Bp2[nd2 * 32 + lane];
        float vA0 = d_V[nd * 3 + 0],  vA1 = d_V[nd * 3 + 1],  vA2 = d_V[nd * 3 + 2];
        float vB0 = d_V[nd2 * 3 + 0], vB1 = d_V[nd2 * 3 + 1], vB2 = d_V[nd2 * 3 + 2];
        s1x = fmaf(odA, aA.x, s1x);         s1y = fmaf(odA, aA.y, s1y);
        s2x = fmaf(idA, bpA.x, s2x);        s2y = fmaf(idA, bpA.y, s2y);
        s3x = fmaf(odA * aA.x, aA.x, s3x);  s3y = fmaf(odA * aA.y, aA.y, s3y);
        float oAx = bias.x - bpA.x, oAy = bias.y - bpA.y;
        s4x = fmaf(idA * oAx, oAx, s4x);    s4y = fmaf(idA * oAy, oAy, s4y);
        float bvAx = vA0 * w61.x + vA1 * w62.x + vA2 * w63.x;
        float bvAy = vA0 * w61.y + vA1 * w62.y + vA2 * w63.y;
        s5x = fmaf(aA.x, bvAx, s5x);        s5y = fmaf(aA.y, bvAy, s5y);
        s1x = fmaf(odB, aB.x, s1x);         s1y = fmaf(odB, aB.y, s1y);
        s2x = fmaf(idB, bpB.x, s2x);        s2y = fmaf(idB, bpB.y, s2y);
        s3x = fmaf(odB * aB.x, aB.x, s3x);  s3y = fmaf(odB * aB.y, aB.y, s3y);
        float oBx = bias.x - bpB.x, oBy = bias.y - bpB.y;
        s4x = fmaf(idB * oBx, oBx, s4x);    s4y = fmaf(idB * oBy, oBy, s4y);
        float bvBx = vB0 * w61.x + vB1 * w62.x + vB2 * w63.x;
        float bvBy = vB0 * w61.y + vB1 * w62.y + vB2 * w63.y;
        s5x = fmaf(aB.x, bvBx, s5x);        s5y = fmaf(aB.y, bvBy, s5y);
    }
    if (nd < n) {
        float od = (float)d_odeg[nd];
        float id = (float)d_deg[nd];
        float2 a  = __half22float2(Ah2[nd * 32 + lane]);
        float2 bp = Bp2[nd * 32 + lane];
        float v0 = d_V[nd * 3 + 0], v1 = d_V[nd * 3 + 1], v2 = d_V[nd * 3 + 2];
        s1x = fmaf(od, a.x, s1x);          s1y = fmaf(od, a.y, s1y);
        s2x = fmaf(id, bp.x, s2x);         s2y = fmaf(id, bp.y, s2y);
        s3x = fmaf(od * a.x, a.x, s3x);    s3y = fmaf(od * a.y, a.y, s3y);
        float ox = bias.x - bp.x, oy = bias.y - bp.y;
        s4x = fmaf(id * ox, ox, s4x);      s4y = fmaf(id * oy, oy, s4y);
        float bvx = v0 * w61.x + v1 * w62.x + v2 * w63.x;
        float bvy = v0 * w61.y + v1 * w62.y + v2 * w63.y;
        s5x = fmaf(a.x, bvx, s5x);         s5y = fmaf(a.y, bvy, s5y);
    }
    atomicAdd(&d_s1[2 * lane], s1x);     atomicAdd(&d_s1[2 * lane + 1], s1y);
    atomicAdd(&d_s2[2 * lane], s2x);     atomicAdd(&d_s2[2 * lane + 1], s2y);
    atomicAdd(&d_s3[2 * lane], s3x);     atomicAdd(&d_s3[2 * lane + 1], s3y);
    atomicAdd(&d_s4[2 * lane], s4x);     atomicAdd(&d_s4[2 * lane + 1], s4y);
    atomicAdd(&d_s5[2 * lane], s5x);     atomicAdd(&d_s5[2 * lane + 1], s5y);
}

// ------------- K6: finalize BN1 params (b1 folded into shift) -------------
__global__ void k_bn1(const float* __restrict__ g1, const float* __restrict__ be1,
                      const float* __restrict__ b1, float Ef) {
    int c = threadIdx.x;
    float bc = b1[c];
    float sumz  = d_s1[c] + Ef * bc - d_s2[c];
    float sumz2 = d_s3[c] + d_s4[c] + 2.0f * (bc * d_s1[c] - d_s5[c]);
    float mu  = sumz / Ef;
    float var = sumz2 / Ef - mu * mu;
    float sc  = g1[c] * rsqrtf(var + BN_EPS);
    ((float*)d_scale1)[c] = sc;
    ((float*)d_shift1)[c] = be1[c] + (bc - mu) * sc;
}

// ------------- K7: gate (quarter-warp per edge, 8 edges/iter) -------------
__global__ void k_gate(const float* __restrict__ Wg, const float* __restrict__ bg, int n) {
    int lane = threadIdx.x & 31;
    int q  = lane >> 3;
    int ql = lane & 7;
    int wid  = (blockIdx.x * blockDim.x + threadIdx.x) >> 5;
    int nw   = (gridDim.x * blockDim.x) >> 5;
    float4 scA = d_scale1[ql * 2], scB = d_scale1[ql * 2 + 1];
    float4 shA = d_shift1[ql * 2], shB = d_shift1[ql * 2 + 1];
    float4 wgA = ((const float4*)Wg)[ql * 2], wgB = ((const float4*)Wg)[ql * 2 + 1];
    float bgv = bg[0];
    float sg = 0.f, sg2 = 0.f;
    for (int nd = wid; nd < n; nd += nw) {
        int r0 = d_rowptr[nd], r1 = d_rowptr[nd + 1];
        if (r0 == r1) continue;
        float4 bpA = d_Bp4[nd * 16 + ql * 2];
        float4 bpB = d_Bp4[nd * 16 + ql * 2 + 1];
        float4 oA = make_float4(fmaf(-bpA.x, scA.x, shA.x), fmaf(-bpA.y, scA.y, shA.y),
                                fmaf(-bpA.z, scA.z, shA.z), fmaf(-bpA.w, scA.w, shA.w));
        float4 oB = make_float4(fmaf(-bpB.x, scB.x, shB.x), fmaf(-bpB.y, scB.y, shB.y),
                                fmaf(-bpB.z, scB.z, shB.z), fmaf(-bpB.w, scB.w, shB.w));
        int j = r0;
        for (; j + 8 <= r1; j += 8) {
            int s0 = d_csrc[j + q];
            int s1 = d_csrc[j + 4 + q];
            uint4 raw0 = d_Ah[s0 * 8 + ql];
            uint4 raw1 = d_Ah[s1 * 8 + ql];
            float p0 = dot8(raw0, oA, oB, scA, scB, wgA, wgB);
            float p1 = dot8(raw1, oA, oB, scA, scB, wgA, wgB);
            #pragma unroll
            for (int off = 4; off; off >>= 1) {
                p0 += __shfl_xor_sync(0xffffffffu, p0, off);
                p1 += __shfl_xor_sync(0xffffffffu, p1, off);
            }
            if (ql == 0) {
                p0 += bgv; p1 += bgv;
                d_graw[j + q] = p0;
                d_graw[j + 4 + q] = p1;
                sg += p0 + p1;
                sg2 = fmaf(p0, p0, sg2);
                sg2 = fmaf(p1, p1, sg2);
            }
        }
        if (j + 4 <= r1) {
            int s = d_csrc[j + q];
            uint4 raw = d_Ah[s * 8 + ql];
            float p = dot8(raw, oA, oB, scA, scB, wgA, wgB);
            #pragma unroll
            for (int off = 4; off; off >>= 1)
                p += __shfl_xor_sync(0xffffffffu, p, off);
            if (ql == 0) {
                p += bgv;
                d_graw[j + q] = p;
                sg += p;
                sg2 = fmaf(p, p, sg2);
            }
            j += 4;
        }
        int rem = r1 - j;
        if (rem > 0) {
            bool act = (q < rem);
            int jj = j + (act ? q : 0);
            int s = d_csrc[jj];
            uint4 raw = d_Ah[s * 8 + ql];
            float p = dot8(raw, oA, oB, scA, scB, wgA, wgB);
            #pragma unroll
            for (int off = 4; off; off >>= 1)
                p += __shfl_xor_sync(0xffffffffu, p, off);
            if (ql == 0 && act) {
                p += bgv;
                d_graw[jj] = p;
                sg += p;
                sg2 = fmaf(p, p, sg2);
            }
        }
    }
    sg  += __shfl_xor_sync(0xffffffffu, sg, 8);
    sg2 += __shfl_xor_sync(0xffffffffu, sg2, 8);
    sg  += __shfl_xor_sync(0xffffffffu, sg, 16);
    sg2 += __shfl_xor_sync(0xffffffffu, sg2, 16);
    if (lane == 0) {
        atomicAdd(&d_gstats[0], sg);
        atomicAdd(&d_gstats[1], sg2);
    }
}

// ------------- K8 -------------
__global__ void k_bng(const float* __restrict__ gg, const float* __restrict__ bgb, float Ef) {
    float mu  = d_gstats[0] / Ef;
    float var = d_gstats[1] / Ef - mu * mu;
    float sc  = gg[0] * rsqrtf(var + BN_EPS);
    d_gparams[0] = sc;
    d_gparams[1] = bgb[0] - mu * sc;
}

// ------------- K9: fused softmax + aggregate, single sweep, in-lane weights -------------
__global__ void k_agg(float* __restrict__ out, int n) {
    int lane = threadIdx.x & 31;
    int q  = lane >> 3;
    int ql = lane & 7;
    int wid  = (blockIdx.x * blockDim.x + threadIdx.x) >> 5;
    int nw   = (gridDim.x * blockDim.x) >> 5;
    float4 scA = d_scale1[ql * 2], scB = d_scale1[ql * 2 + 1];
    float4 shA = d_shift1[ql * 2], shB = d_shift1[ql * 2 + 1];
    float gsc = d_gparams[0], gsh = d_gparams[1];
    float4* out4 = (float4*)out;
    for (int nd = wid; nd < n; nd += nw) {
        int r0 = d_rowptr[nd], r1 = d_rowptr[nd + 1];
        if (r0 == r1) {
            if (q == 0) {
                out4[nd * 16 + ql * 2]     = make_float4(0.f, 0.f, 0.f, 0.f);
                out4[nd * 16 + ql * 2 + 1] = make_float4(0.f, 0.f, 0.f, 0.f);
            }
            continue;
        }
        float4 bpA = d_Bp4[nd * 16 + ql * 2];
        float4 bpB = d_Bp4[nd * 16 + ql * 2 + 1];
        float4 oA = make_float4(fmaf(-bpA.x, scA.x, shA.x), fmaf(-bpA.y, scA.y, shA.y),
                                fmaf(-bpA.z, scA.z, shA.z), fmaf(-bpA.w, scA.w, shA.w));
        float4 oB = make_float4(fmaf(-bpB.x, scB.x, shB.x), fmaf(-bpB.y, scB.y, shB.y),
                                fmaf(-bpB.z, scB.z, shB.z), fmaf(-bpB.w, scB.w, shB.w));
        float4 accA = make_float4(0.f, 0.f, 0.f, 0.f);
        float4 accB = make_float4(0.f, 0.f, 0.f, 0.f);
        float ssum = 0.f;
        int j = r0;
        for (; j + 8 <= r1; j += 8) {
            int s0 = d_csrc[j + q];
            int s1 = d_csrc[j + 4 + q];
            float gr0 = d_graw[j + q];
            float gr1 = d_graw[j + 4 + q];
            uint4 raw0 = d_Ah[s0 * 8 + ql];
            uint4 raw1 = d_Ah[s1 * 8 + ql];
            float e0 = __expf(silu_f(fmaf(gr0, gsc, gsh)));
            float e1 = __expf(silu_f(fmaf(gr1, gsc, gsh)));
            ssum += e0 + e1;
            acc8(raw0, oA, oB, scA, scB, e0, accA, accB);
            acc8(raw1, oA, oB, scA, scB, e1, accA, accB);
        }
        if (j + 4 <= r1) {
            int s = d_csrc[j + q];
            float gr = d_graw[j + q];
            uint4 raw = d_Ah[s * 8 + ql];
            float e = __expf(silu_f(fmaf(gr, gsc, gsh)));
            ssum += e;
            acc8(raw, oA, oB, scA, scB, e, accA, accB);
            j += 4;
        }
        int rem = r1 - j;
        if (rem > 0) {
            bool act = (q < rem);
            int jj = j + (act ? q : 0);
            int s = d_csrc[jj];
            float gr = d_graw[jj];
            uint4 raw = d_Ah[s * 8 + ql];
            float e = act ? __expf(silu_f(fmaf(gr, gsc, gsh))) : 0.0f;
            ssum += e;
            acc8(raw, oA, oB, scA, scB, e, accA, accB);
        }
        ssum += __shfl_xor_sync(0xffffffffu, ssum, 8);
        ssum += __shfl_xor_sync(0xffffffffu, ssum, 16);
        float inv = 1.0f / (ssum + 1e-16f);
        #pragma unroll
        for (int off = 8; off <= 16; off <<= 1) {
            accA.x += __shfl_xor_sync(0xffffffffu, accA.x, off);
            accA.y += __shfl_xor_sync(0xffffffffu, accA.y, off);
            accA.z += __shfl_xor_sync(0xffffffffu, accA.z, off);
            accA.w += __shfl_xor_sync(0xffffffffu, accA.w, off);
            accB.x += __shfl_xor_sync(0xffffffffu, accB.x, off);
            accB.y += __shfl_xor_sync(0xffffffffu, accB.y, off);
            accB.z += __shfl_xor_sync(0xffffffffu, accB.z, off);
            accB.w += __shfl_xor_sync(0xffffffffu, accB.w, off);
        }
        if (q == 0) {
            out4[nd * 16 + ql * 2]     = make_float4(accA.x * inv, accA.y * inv,
                                                     accA.z * inv, accA.w * inv);
            out4[nd * 16 + ql * 2 + 1] = make_float4(accB.x * inv, accB.y * inv,
                                                     accB.z * inv, accB.w * inv);
        }
    }
}

// ------------- launch: two-stream DAG -------------
// main: init -> count(+V) -> scanA/B/C -> scatter ----\
//                                                       join -> gate -> bng -> agg
// side: node --------------(wait count)--> zstats -> bn1 /
extern "C" void kernel_launch(void* const* d_in, const int* in_sizes, int n_in,
                              void* d_out, int out_size) {
    const float* x   = (const float*)d_in[0];
    const float* pos = (const float*)d_in[1];
    const int*   ei  = (const int*)d_in[2];
    const float* W1  = (const float*)d_in[3];
    const float* b1  = (const float*)d_in[4];
    const float* g1  = (const float*)d_in[5];
    const float* be1 = (const float*)d_in[6];
    const float* Wg  = (const float*)d_in[7];
    const float* bg  = (const float*)d_in[8];
    const float* gg  = (const float*)d_in[9];
    const float* bgb = (const float*)d_in[10];
    float* out = (float*)d_out;

    int n = in_sizes[0] / INCH;   // 100000
    int e = in_sizes[2] / 2;      // 1600000
    int nb = (n + SCAN_BLK - 1) / SCAN_BLK;

    // fork side stream: k_node runs concurrent with init/count
    cudaEventRecord(g_fr.fork, 0);
    cudaStreamWaitEvent(g_fr.s, g_fr.fork, 0);
    k_node<<<512, 256, 0, g_fr.s>>>(x, pos, W1, n);

    // main chain: init + count (+V)
    k_init <<<256, 256>>>(n);
    k_count<<<512, 256>>>(ei, pos, e, n);
    cudaEventRecord(g_fr.ecnt, 0);

    // side chain: zstats + bn1 (needs node done [stream order] + count done [event])
    cudaStreamWaitEvent(g_fr.s, g_fr.ecnt, 0);
    k_zstats<<<256, 256, 0, g_fr.s>>>(b1, W1, n);
    k_bn1   <<<1, 64, 0, g_fr.s>>>(g1, be1, b1, (float)e);
    cudaEventRecord(g_fr.join, g_fr.s);

    // main chain: scan + scatter (concurrent with zstats/bn1)
    k_scanA  <<<nb, SCAN_BLK>>>(n);
    k_scanB  <<<1, 128>>>(nb, n);
    k_scanC  <<<nb, SCAN_BLK>>>(n);
    k_scatter<<<512, 256>>>(ei, e, n);

    // join: gate needs bn1 params (side) + csrc (main)
    cudaStreamWaitEvent(0, g_fr.join, 0);

    k_gate<<<1024, 256>>>(Wg, bg, n);
    k_bng <<<1, 1>>>(gg, bgb, (float)e);
    k_agg <<<1024, 256>>>(out, n);
}